// round 17
// baseline (speedup 1.0000x reference)
#include <cuda_runtime.h>
#include <cuda_bf16.h>
#include <cstdint>

#define BATCH 2
#define SEQ   2048
#define DIM   2048
#define NH    16
#define HD    128
#define ROWS  (BATCH*SEQ)   // 4096
#define NSM   148
#define NITEM 512           // 16 qt x 16 h x 2 b

// ---------------- scratch (static device globals; no allocs allowed) --------
__device__ __nv_bfloat16 g_xhi[ROWS*DIM];
__device__ __nv_bfloat16 g_xlo[ROWS*DIM];
__device__ __nv_bfloat16 g_ohi[ROWS*DIM];
__device__ __nv_bfloat16 g_olo[ROWS*DIM];
__device__ __nv_bfloat16 g_whi[4][DIM*DIM];   // q,k,v,o
__device__ __nv_bfloat16 g_wlo[4][DIM*DIM];

__device__ __nv_bfloat16 g_qhi[ROWS*DIM];
__device__ __nv_bfloat16 g_qlo[ROWS*DIM];
__device__ __nv_bfloat16 g_khi[ROWS*DIM];
__device__ __nv_bfloat16 g_klo[ROWS*DIM];
__device__ __nv_bfloat16 g_vthi[ROWS*DIM];    // per-head transposed [b,h,d,s]
__device__ __nv_bfloat16 g_vtlo[ROWS*DIM];

// ============================================================================
// helpers
// ============================================================================
__device__ __forceinline__ void cp_async16(void* smem, const void* gmem) {
    uint32_t s = (uint32_t)__cvta_generic_to_shared(smem);
    asm volatile("cp.async.cg.shared.global [%0], [%1], 16;\n" :: "r"(s), "l"(gmem));
}
__device__ __forceinline__ void cp_async16_s(uint32_t saddr, const void* gmem) {
    asm volatile("cp.async.cg.shared.global [%0], [%1], 16;\n" :: "r"(saddr), "l"(gmem));
}

__device__ __forceinline__ void mma_bf16(float* c, const uint32_t* a, const uint32_t* b) {
    asm volatile(
        "mma.sync.aligned.m16n8k16.row.col.f32.bf16.bf16.f32 "
        "{%0,%1,%2,%3}, {%4,%5,%6,%7}, {%8,%9}, {%0,%1,%2,%3};\n"
        : "+f"(c[0]), "+f"(c[1]), "+f"(c[2]), "+f"(c[3])
        : "r"(a[0]), "r"(a[1]), "r"(a[2]), "r"(a[3]),
          "r"(b[0]), "r"(b[1]));
}
__device__ __forceinline__ void ldsm_x4(uint32_t* r, uint32_t saddr) {
    asm volatile("ldmatrix.sync.aligned.m8n8.x4.shared.b16 {%0,%1,%2,%3}, [%4];"
        : "=r"(r[0]), "=r"(r[1]), "=r"(r[2]), "=r"(r[3]) : "r"(saddr));
}
__device__ __forceinline__ uint32_t smem_u32(const void* p) {
    return (uint32_t)__cvta_generic_to_shared(p);
}

// ---- mbarrier ---------------------------------------------------------------
#define MBAR_INIT(addr, cnt) \
    asm volatile("mbarrier.init.shared.b64 [%0], %1;" :: "r"(addr), "r"(cnt) : "memory")
#define MBAR_ARRIVE(addr) \
    asm volatile("{\n\t.reg .b64 st;\n\tmbarrier.arrive.shared.b64 st, [%0];\n\t}" \
                 :: "r"(addr) : "memory")
// .noinc: async arrive counts against the initialized expected count and
// covers ALL prior cp.asyncs issued by this thread.
#define CP_ASYNC_MBAR_ARRIVE(addr) \
    asm volatile("cp.async.mbarrier.arrive.noinc.shared.b64 [%0];" :: "r"(addr) : "memory")
// Bounded spin: protocol bugs fail fast (wrong answer), never hang containers.
#define MBAR_WAIT(addr, parity) do {                                            \
    uint32_t _done = 0; uint32_t _spin = 0;                                     \
    while (!_done && _spin < (1u << 24)) {                                      \
        asm volatile(                                                           \
            "{\n\t.reg .pred p;\n\t"                                            \
            "mbarrier.try_wait.parity.shared.b64 p, [%1], %2;\n\t"              \
            "selp.b32 %0, 1, 0, p;\n\t}"                                        \
            : "=r"(_done) : "r"(addr), "r"(parity) : "memory");                 \
        _spin++;                                                                \
    }                                                                           \
} while (0)

// ---------------- fp32 -> bf16 hi/lo split (x) -------------------------------
__global__ void split_kernel(const float* __restrict__ in,
                             __nv_bfloat16* __restrict__ hi,
                             __nv_bfloat16* __restrict__ lo, int n4)
{
    int idx = blockIdx.x * blockDim.x + threadIdx.x;
    if (idx >= n4) return;
    float4 v = ((const float4*)in)[idx];
    __nv_bfloat16 h0 = __float2bfloat16(v.x);
    __nv_bfloat16 h1 = __float2bfloat16(v.y);
    __nv_bfloat16 h2 = __float2bfloat16(v.z);
    __nv_bfloat16 h3 = __float2bfloat16(v.w);
    __nv_bfloat16 l0 = __float2bfloat16(v.x - __bfloat162float(h0));
    __nv_bfloat16 l1 = __float2bfloat16(v.y - __bfloat162float(h1));
    __nv_bfloat16 l2 = __float2bfloat16(v.z - __bfloat162float(h2));
    __nv_bfloat16 l3 = __float2bfloat16(v.w - __bfloat162float(h3));
    ((__nv_bfloat162*)hi)[idx*2+0] = __nv_bfloat162(h0, h1);
    ((__nv_bfloat162*)hi)[idx*2+1] = __nv_bfloat162(h2, h3);
    ((__nv_bfloat162*)lo)[idx*2+0] = __nv_bfloat162(l0, l1);
    ((__nv_bfloat162*)lo)[idx*2+1] = __nv_bfloat162(l2, l3);
}

// ---------------- fused 4-weight split (grid.y selects weight) ---------------
__global__ void split4_kernel(const float* __restrict__ w0,
                              const float* __restrict__ w1,
                              const float* __restrict__ w2,
                              const float* __restrict__ w3,
                              __nv_bfloat16* __restrict__ hib,
                              __nv_bfloat16* __restrict__ lob, int n4)
{
    int idx = blockIdx.x * blockDim.x + threadIdx.x;
    if (idx >= n4) return;
    int wsel = blockIdx.y;
    const float* in = (wsel == 0) ? w0 : (wsel == 1) ? w1 : (wsel == 2) ? w2 : w3;
    __nv_bfloat16* hi = hib + (size_t)wsel * DIM * DIM;
    __nv_bfloat16* lo = lob + (size_t)wsel * DIM * DIM;
    float4 v = ((const float4*)in)[idx];
    __nv_bfloat16 h0 = __float2bfloat16(v.x);
    __nv_bfloat16 h1 = __float2bfloat16(v.y);
    __nv_bfloat16 h2 = __float2bfloat16(v.z);
    __nv_bfloat16 h3 = __float2bfloat16(v.w);
    __nv_bfloat16 l0 = __float2bfloat16(v.x - __bfloat162float(h0));
    __nv_bfloat16 l1 = __float2bfloat16(v.y - __bfloat162float(h1));
    __nv_bfloat16 l2 = __float2bfloat16(v.z - __bfloat162float(h2));
    __nv_bfloat16 l3 = __float2bfloat16(v.w - __bfloat162float(h3));
    ((__nv_bfloat162*)hi)[idx*2+0] = __nv_bfloat162(h0, h1);
    ((__nv_bfloat162*)hi)[idx*2+1] = __nv_bfloat162(h2, h3);
    ((__nv_bfloat162*)lo)[idx*2+0] = __nv_bfloat162(l0, l1);
    ((__nv_bfloat162*)lo)[idx*2+1] = __nv_bfloat162(l2, l3);
}

// ============================================================================
// R17 GEMM: warp-specialized producer/consumer, 6-stage mbarrier pipeline.
// 384 threads: warps 0-7 consume (ldsm+mma only), warps 8-11 produce (cp.async).
// No __syncthreads / wait_group in the mainloop.  C = (Ahi+Alo)(Bhi+Blo)^T.
// ============================================================================
#define BM 128
#define BN 128
#define BK 32
#define GNSTG 6
#define TILE_B (BM*BK*2)                  // 8192 B per array per stage
#define G_MBAR  (4*GNSTG*TILE_B)          // 196608
#define GEMM_SMEM_BYTES (G_MBAR + GNSTG*16)   // + 6 full/empty pairs

__device__ __forceinline__ uint32_t swz(int row, int chunk) {
    return (uint32_t)(row * 64 + ((chunk ^ ((row >> 1) & 3)) << 4));
}

struct GemmWS {
    uint32_t uAh, uAl, uBh, uBl, umb;
    int t, lane, wid, gid, tig, wm, wn, m0, n0;
    int arow, achk, brow, bchk;
    float acc[4][4][4];

    __device__ __forceinline__ void init(char* smc, int bx, int by, int tid) {
        uAh = smem_u32(smc);
        uAl = uAh + GNSTG * TILE_B;
        uBh = uAh + 2 * GNSTG * TILE_B;
        uBl = uAh + 3 * GNSTG * TILE_B;
        umb = uAh + G_MBAR;
        t = tid; lane = t & 31; wid = t >> 5;
        gid = lane >> 2; tig = lane & 3;
        wm = (wid & 1) * 64; wn = ((wid >> 1) & 3) * 32;
        m0 = by * BM; n0 = bx * BN;
        arow = lane & 15; achk = lane >> 4;
        brow = ((lane >> 4) << 3) + (lane & 7);
        bchk = (lane >> 3) & 1;
#pragma unroll
        for (int i = 0; i < 4; i++)
#pragma unroll
            for (int j = 0; j < 4; j++)
#pragma unroll
                for (int e = 0; e < 4; e++) acc[i][j][e] = 0.f;
    }

    __device__ __forceinline__ uint32_t full_b(int s)  { return umb + s * 16; }
    __device__ __forceinline__ uint32_t empty_b(int s) { return umb + s * 16 + 8; }

    // producer: thread pt (0..127) loads row pt (4 chunks) of each array
    __device__ __forceinline__ void load_stage_p(
        int s, int k0, int pt,
        const __nv_bfloat16* Ahi, const __nv_bfloat16* Alo,
        const __nv_bfloat16* Bhi, const __nv_bfloat16* Blo, int K)
    {
        const uint32_t sb = s * TILE_B;
        size_t ga = (size_t)(m0 + pt) * K + k0;
        size_t gb = (size_t)(n0 + pt) * K + k0;
#pragma unroll
        for (int c = 0; c < 4; c++) {
            uint32_t so = sb + swz(pt, c);
            cp_async16_s(uAh + so, Ahi + ga + c * 8);
            cp_async16_s(uAl + so, Alo + ga + c * 8);
            cp_async16_s(uBh + so, Bhi + gb + c * 8);
            cp_async16_s(uBl + so, Blo + gb + c * 8);
        }
    }

    __device__ __forceinline__ void consume_stage(int stg) {
        const uint32_t stb = stg * TILE_B;
#pragma unroll
        for (int kk = 0; kk < 2; kk++) {
            uint32_t ah[4][4], al[4][4], bh[4][2], bl[4][2];
#pragma unroll
            for (int ms = 0; ms < 4; ms++) {
                int row = wm + ms * 16 + arow;
                uint32_t off = stb + swz(row, 2 * kk + achk);
                ldsm_x4(ah[ms], uAh + off);
                ldsm_x4(al[ms], uAl + off);
            }
#pragma unroll
            for (int nsp = 0; nsp < 2; nsp++) {
                int row = wn + nsp * 16 + brow;
                uint32_t off = stb + swz(row, 2 * kk + bchk);
                uint32_t r[4];
                ldsm_x4(r, uBh + off);
                bh[2*nsp][0] = r[0]; bh[2*nsp][1] = r[1];
                bh[2*nsp+1][0] = r[2]; bh[2*nsp+1][1] = r[3];
                ldsm_x4(r, uBl + off);
                bl[2*nsp][0] = r[0]; bl[2*nsp][1] = r[1];
                bl[2*nsp+1][0] = r[2]; bl[2*nsp+1][1] = r[3];
            }
#pragma unroll
            for (int ms = 0; ms < 4; ms++)
#pragma unroll
                for (int ns = 0; ns < 4; ns++) {
                    mma_bf16(acc[ms][ns], ah[ms], bh[ns]);
                    mma_bf16(acc[ms][ns], al[ms], bh[ns]);
                    mma_bf16(acc[ms][ns], ah[ms], bl[ns]);
                }
        }
    }

    // returns true for producer threads (they are done after this)
    __device__ __forceinline__ bool run(
        char* smc,
        const __nv_bfloat16* Ahi, const __nv_bfloat16* Alo,
        const __nv_bfloat16* Bhi, const __nv_bfloat16* Blo, int K)
    {
        const int NK = K / BK;   // 64
        if (t == 0) {
#pragma unroll
            for (int s = 0; s < GNSTG; s++) {
                MBAR_INIT(full_b(s), 128);
                MBAR_INIT(empty_b(s), 256);
            }
        }
        __syncthreads();

        if (wid >= 8) {
            // -------- producer --------
            const int pt = t - 256;
            for (int base = 0, g = 0; base < NK; base += GNSTG, g++) {
#pragma unroll
                for (int s = 0; s < GNSTG; s++) {
                    int kt = base + s;
                    if (kt >= NK) break;
                    if (g > 0) MBAR_WAIT(empty_b(s), (g - 1) & 1);
                    load_stage_p(s, kt * BK, pt, Ahi, Alo, Bhi, Blo, K);
                    CP_ASYNC_MBAR_ARRIVE(full_b(s));
                }
            }
            return true;
        }

        // -------- consumer --------
        for (int base = 0, g = 0; base < NK; base += GNSTG, g++) {
#pragma unroll
            for (int s = 0; s < GNSTG; s++) {
                int kt = base + s;
                if (kt >= NK) break;
                MBAR_WAIT(full_b(s), g & 1);
                consume_stage(s);
                MBAR_ARRIVE(empty_b(s));
            }
        }
        return false;
    }
};

__device__ __forceinline__ void split_store2(
    __nv_bfloat16* hi, __nv_bfloat16* lo, size_t idx2, float x, float y)
{
    __nv_bfloat16 hx = __float2bfloat16(x);
    __nv_bfloat16 hy = __float2bfloat16(y);
    ((__nv_bfloat162*)hi)[idx2] = __nv_bfloat162(hx, hy);
    ((__nv_bfloat162*)lo)[idx2] = __nv_bfloat162(
        __float2bfloat16(x - __bfloat162float(hx)),
        __float2bfloat16(y - __bfloat162float(hy)));
}

// proj 0=Q(rope), 1=K(rope), 2=V^T (A/B swapped, scatter to [b,h,d,s])
__global__ void __launch_bounds__(384, 1) gemm_qkv(
    const __nv_bfloat16* __restrict__ xhi, const __nv_bfloat16* __restrict__ xlo,
    const __nv_bfloat16* __restrict__ whi, const __nv_bfloat16* __restrict__ wlo,
    __nv_bfloat16* __restrict__ qhi, __nv_bfloat16* __restrict__ qlo,
    __nv_bfloat16* __restrict__ khi, __nv_bfloat16* __restrict__ klo,
    __nv_bfloat16* __restrict__ vthi, __nv_bfloat16* __restrict__ vtlo,
    const float* __restrict__ fc, const float* __restrict__ fs)
{
    extern __shared__ char smc[];
    const int proj = blockIdx.z;
    GemmWS g;
    const __nv_bfloat16* Whi = whi + (size_t)proj * DIM * DIM;
    const __nv_bfloat16* Wlo = wlo + (size_t)proj * DIM * DIM;

    if (proj == 2) {
        g.init(smc, blockIdx.y, blockIdx.x, threadIdx.x);
        if (g.run(smc, Whi, Wlo, xhi, xlo, DIM)) return;
#pragma unroll
        for (int ms = 0; ms < 4; ms++)
#pragma unroll
            for (int ns = 0; ns < 4; ns++) {
                int e0 = g.m0 + g.wm + ms * 16 + g.gid;
                int sg = g.n0 + g.wn + ns * 8 + g.tig * 2;
                int b  = sg >> 11;
                int sl = sg & (SEQ - 1);
#pragma unroll
                for (int half = 0; half < 2; half++) {
                    int e = e0 + half * 8;
                    size_t off = (size_t)b * DIM * SEQ + (size_t)e * SEQ + sl;
                    split_store2(vthi, vtlo, off >> 1,
                                 g.acc[ms][ns][half * 2], g.acc[ms][ns][half * 2 + 1]);
                }
            }
        return;
    }

    g.init(smc, blockIdx.x, blockIdx.y, threadIdx.x);
    if (g.run(smc, xhi, xlo, Whi, Wlo, DIM)) return;
    const int N = DIM;
    __nv_bfloat16* Chi = proj ? khi : qhi;
    __nv_bfloat16* Clo = proj ? klo : qlo;
#pragma unroll
    for (int ms = 0; ms < 4; ms++)
#pragma unroll
        for (int ns = 0; ns < 4; ns++) {
            int row0 = g.m0 + g.wm + ms * 16 + g.gid;
            int col  = g.n0 + g.wn + ns * 8 + g.tig * 2;
            int i = (col & 127) >> 1;
#pragma unroll
            for (int half = 0; half < 2; half++) {
                int row = row0 + half * 8;
                int s   = row & (SEQ - 1);
                float cs = __ldg(fc + s * 64 + i);
                float sn = __ldg(fs + s * 64 + i);
                float re = g.acc[ms][ns][half * 2];
                float im = g.acc[ms][ns][half * 2 + 1];
                float rx = re * cs - im * sn;
                float ry = re * sn + im * cs;
                split_store2(Chi, Clo, ((size_t)row * N + col) >> 1, rx, ry);
            }
        }
}

__global__ void __launch_bounds__(384, 1) gemm_out(
    const __nv_bfloat16* __restrict__ Ahi, const __nv_bfloat16* __restrict__ Alo,
    const __nv_bfloat16* __restrict__ Bhi, const __nv_bfloat16* __restrict__ Blo,
    float* __restrict__ C)
{
    extern __shared__ char smc[];
    GemmWS g;
    g.init(smc, blockIdx.x, blockIdx.y, threadIdx.x);
    if (g.run(smc, Ahi, Alo, Bhi, Blo, DIM)) return;
    const int N = DIM;
#pragma unroll
    for (int ms = 0; ms < 4; ms++)
#pragma unroll
        for (int ns = 0; ns < 4; ns++) {
            int row = g.m0 + g.wm + ms * 16 + g.gid;
            int col = g.n0 + g.wn + ns * 8 + g.tig * 2;
            float2 c0 = {g.acc[ms][ns][0], g.acc[ms][ns][1]};
            float2 c1 = {g.acc[ms][ns][2], g.acc[ms][ns][3]};
            *(float2*)&C[(size_t)row * N + col]       = c0;
            *(float2*)&C[(size_t)(row + 8) * N + col] = c1;
        }
}

// ============================================================================
// PERSISTENT warp-specialized flash attention, bf16x3, causal (R16, unchanged)
// ============================================================================
#define AQ  128
#define AK  64
#define AHS 136
#define AVS 72
#define A_QH        0
#define A_QL        17408
#define A_KH(bf)    (34816 + (bf)*8704)
#define A_KL(bf)    (52224 + (bf)*8704)
#define A_VH(bf)    (69632 + (bf)*9216)
#define A_VL(bf)    (88064 + (bf)*9216)
#define A_MBAR_B    212992
#define ATTN_SMEM_BYTES (212992 + 64)

__global__ void __launch_bounds__(384) attn_tc_kernel(
    const __nv_bfloat16* __restrict__ qhi, const __nv_bfloat16* __restrict__ qlo,
    const __nv_bfloat16* __restrict__ khi, const __nv_bfloat16* __restrict__ klo,
    const __nv_bfloat16* __restrict__ vthi, const __nv_bfloat16* __restrict__ vtlo,
    __nv_bfloat16* __restrict__ ohi, __nv_bfloat16* __restrict__ olo)
{
    extern __shared__ __nv_bfloat16 smh[];
    const uint32_t ubase = smem_u32(smh);
    const uint32_t mb_full0  = ubase + A_MBAR_B;
    const uint32_t mb_full1  = ubase + A_MBAR_B + 8;
    const uint32_t mb_empty0 = ubase + A_MBAR_B + 16;
    const uint32_t mb_empty1 = ubase + A_MBAR_B + 24;
    const uint32_t mb_qfree  = ubase + A_MBAR_B + 32;

    const int t    = threadIdx.x;
    const int lane = t & 31;
    const int wid  = t >> 5;
    const int gid  = lane >> 2;
    const int tig  = lane & 3;
    const int cta  = blockIdx.x;

    const int arow = (lane & 15);
    const int acol = (lane >> 4) << 3;
    const int brow = ((lane >> 4) << 3) + (lane & 7);
    const int bcol = ((lane >> 3) & 1) << 3;

    if (t == 0) {
        MBAR_INIT(mb_full0, 128);
        MBAR_INIT(mb_full1, 128);
        MBAR_INIT(mb_empty0, 256);
        MBAR_INIT(mb_empty1, 256);
        MBAR_INIT(mb_qfree, 256);
    }
    __syncthreads();

    const float scale2 = 0.08838834764831845f * 1.4426950408889634f;

    if (wid >= 8) {
        const int pt = t - 256;
        int ep0 = 0, ep1 = 0, qph = 0;
        bool first = true;

#define LOAD_KV_P(BUFI, KT, B_, H_)                                             \
        {                                                                       \
            int row = pt >> 1;                                                  \
            int cb  = (pt & 1) * 8;                                             \
            size_t g = (size_t)((B_) * SEQ + (KT) * AK + row) * DIM + (H_) * HD + cb * 8; \
            int so = row * AHS + cb * 8;                                        \
            _Pragma("unroll")                                                   \
            for (int c = 0; c < 8; c++) {                                       \
                cp_async16(smh + A_KH(BUFI) + so + c * 8, khi + g + c * 8);     \
                cp_async16(smh + A_KL(BUFI) + so + c * 8, klo + g + c * 8);     \
            }                                                                   \
            size_t gv = (size_t)(((B_) * NH + (H_)) * HD + pt) * SEQ + (KT) * AK; \
            int sv = pt * AVS;                                                  \
            _Pragma("unroll")                                                   \
            for (int c = 0; c < 8; c++) {                                       \
                cp_async16(smh + A_VH(BUFI) + sv + c * 8, vthi + gv + c * 8);   \
                cp_async16(smh + A_VL(BUFI) + sv + c * 8, vtlo + gv + c * 8);   \
            }                                                                   \
        }

        for (int j = 0; j < 4; j++) {
            int p = (j & 1) ? ((j + 1) * NSM - 1 - cta) : (j * NSM + cta);
            if (p >= NITEM) continue;
            const int qt = 15 - (p >> 5);
            const int hb = p & 31;
            const int h = hb >> 1, b = hb & 1;
            const int ktmax = 2 * qt + 1;

            if (!first) { MBAR_WAIT(mb_qfree, qph); qph ^= 1; }

            {
                size_t g = (size_t)(b * SEQ + qt * AQ + pt) * DIM + h * HD;
                int so = pt * AHS;
#pragma unroll
                for (int c = 0; c < 16; c++) {
                    cp_async16(smh + A_QH + so + c * 8, qhi + g + c * 8);
                    cp_async16(smh + A_QL + so + c * 8, qlo + g + c * 8);
                }
            }
            if (!first) { MBAR_WAIT(mb_empty0, ep0); ep0 ^= 1; }
            LOAD_KV_P(0, 0, b, h);
            CP_ASYNC_MBAR_ARRIVE(mb_full0);
            if (!first) { MBAR_WAIT(mb_empty1, ep1); ep1 ^= 1; }
            LOAD_KV_P(1, 1, b, h);
            CP_ASYNC_MBAR_ARRIVE(mb_full1);
            first = false;

            for (int kt = 2; kt <= ktmax; kt++) {
                const int s = kt & 1;
                if (s == 0) { MBAR_WAIT(mb_empty0, ep0); ep0 ^= 1; }
                else        { MBAR_WAIT(mb_empty1, ep1); ep1 ^= 1; }
                LOAD_KV_P(s, kt, b, h);
                CP_ASYNC_MBAR_ARRIVE(s == 0 ? mb_full0 : mb_full1);
            }
        }
        return;
    }

    int fph0 = 0, fph1 = 0;

    for (int j = 0; j < 4; j++) {
        int p = (j & 1) ? ((j + 1) * NSM - 1 - cta) : (j * NSM + cta);
        if (p >= NITEM) continue;
        const int qt = 15 - (p >> 5);
        const int hb = p & 31;
        const int h = hb >> 1, b = hb & 1;
        const int ktmax = 2 * qt + 1;
        const int gr0 = qt * AQ + wid * 16 + gid;

        float sacc[8][4];
        float oacc[16][4];
#pragma unroll
        for (int i = 0; i < 16; i++)
#pragma unroll
            for (int e = 0; e < 4; e++) oacc[i][e] = 0.f;
        float m0 = -1e30f, m1 = -1e30f, l0 = 0.f, l1 = 0.f;

        for (int kt = 0; kt <= ktmax; kt++) {
            const int s = kt & 1;
            if (s == 0) { MBAR_WAIT(mb_full0, fph0); fph0 ^= 1; }
            else        { MBAR_WAIT(mb_full1, fph1); fph1 ^= 1; }

#pragma unroll
            for (int ns = 0; ns < 8; ns++)
#pragma unroll
                for (int e = 0; e < 4; e++) sacc[ns][e] = 0.f;

            const uint32_t ukh = ubase + A_KH(s) * 2;
            const uint32_t ukl = ubase + A_KL(s) * 2;
#pragma unroll
            for (int kk = 0; kk < 8; kk++) {
                uint32_t aoff = ((wid * 16 + arow) * AHS + kk * 16 + acol) * 2;
                uint32_t ah[4], al[4];
                ldsm_x4(ah, ubase + A_QH * 2 + aoff);
                ldsm_x4(al, ubase + A_QL * 2 + aoff);
#pragma unroll
                for (int nsp = 0; nsp < 4; nsp++) {
                    uint32_t boff = ((nsp * 16 + brow) * AHS + kk * 16 + bcol) * 2;
                    uint32_t rh[4], rl[4];
                    ldsm_x4(rh, ukh + boff);
                    ldsm_x4(rl, ukl + boff);
                    uint32_t b0h[2] = {rh[0], rh[1]}, b1h[2] = {rh[2], rh[3]};
                    uint32_t b0l[2] = {rl[0], rl[1]}, b1l[2] = {rl[2], rl[3]};
                    mma_bf16(sacc[2*nsp],   ah, b0h);
                    mma_bf16(sacc[2*nsp+1], ah, b1h);
                    mma_bf16(sacc[2*nsp],   al, b0h);
                    mma_bf16(sacc[2*nsp+1], al, b1h);
                    mma_bf16(sacc[2*nsp],   ah, b0l);
                    mma_bf16(sacc[2*nsp+1], ah, b1l);
                }
            }

            if (kt * AK + 63 > qt * AQ + wid * 16) {
                int rl0 = gr0 - kt * AK;
                int rl1 = rl0 + 8;
#pragma unroll
                for (int ns = 0; ns < 8; ns++) {
#pragma unroll
                    for (int e = 0; e < 4; e++) {
                        float v = sacc[ns][e] * scale2;
                        int cl = ns * 8 + 2 * tig + (e & 1);
                        int rl = (e < 2) ? rl0 : rl1;
                        sacc[ns][e] = (cl > rl) ? -1e30f : v;
                    }
                }
            } else {
#pragma unroll
                for (int ns = 0; ns < 8; ns++)
#pragma unroll
                    for (int e = 0; e < 4; e++) sacc[ns][e] *= scale2;
            }

            float mx0 = -1e30f, mx1 = -1e30f;
#pragma unroll
            for (int ns = 0; ns < 8; ns++) {
                mx0 = fmaxf(mx0, fmaxf(sacc[ns][0], sacc[ns][1]));
                mx1 = fmaxf(mx1, fmaxf(sacc[ns][2], sacc[ns][3]));
            }
            mx0 = fmaxf(mx0, __shfl_xor_sync(0xffffffffu, mx0, 1));
            mx0 = fmaxf(mx0, __shfl_xor_sync(0xffffffffu, mx0, 2));
            mx1 = fmaxf(mx1, __shfl_xor_sync(0xffffffffu, mx1, 1));
            mx1 = fmaxf(mx1, __shfl_xor_sync(0xffffffffu, mx1, 2));
            float mn0 = fmaxf(m0, mx0), mn1 = fmaxf(m1, mx1);
            float a0 = exp2f(m0 - mn0), a1 = exp2f(m1 - mn1);
            m0 = mn0; m1 = mn1;

            float sum0 = 0.f, sum1 = 0.f;
#pragma unroll
            for (int ns = 0; ns < 8; ns++) {
                float p0 = exp2f(sacc[ns][0] - mn0);
                float p1 = exp2f(sacc[ns][1] - mn0);
                float p2 = exp2f(sacc[ns][2] - mn1);
                float p3 = exp2f(sacc[ns][3] - mn1);
                sacc[ns][0] = p0; sacc[ns][1] = p1;
                sacc[ns][2] = p2; sacc[ns][3] = p3;
                sum0 += p0 + p1; sum1 += p2 + p3;
            }
            sum0 += __shfl_xor_sync(0xffffffffu, sum0, 1);
            sum0 += __shfl_xor_sync(0xffffffffu, sum0, 2);
            sum1 += __shfl_xor_sync(0xffffffffu, sum1, 1);
            sum1 += __shfl_xor_sync(0xffffffffu, sum1, 2);
            l0 = l0 * a0 + sum0;
            l1 = l1 * a1 + sum1;

#pragma unroll
            for (int nd = 0; nd < 16; nd++) {
                oacc[nd][0] *= a0; oacc[nd][1] *= a0;
                oacc[nd][2] *= a1; oacc[nd][3] *= a1;
            }

            const uint32_t uvh = ubase + A_VH(s) * 2;
            const uint32_t uvl = ubase + A_VL(s) * 2;
#pragma unroll
            for (int kc = 0; kc < 4; kc++) {
                uint32_t ph[4], pl[4];
#pragma unroll
                for (int jj = 0; jj < 4; jj++) {
                    int ns = 2 * kc + (jj >> 1);
                    int e0 = (jj & 1) * 2;
                    float c0 = sacc[ns][e0], c1 = sacc[ns][e0 + 1];
                    __nv_bfloat162 hb2 = __floats2bfloat162_rn(c0, c1);
                    uint32_t hu = *(uint32_t*)&hb2;
                    float f0 = __uint_as_float(hu << 16);
                    float f1 = __uint_as_float(hu & 0xffff0000u);
                    __nv_bfloat162 lb = __floats2bfloat162_rn(c0 - f0, c1 - f1);
                    ph[jj] = hu;
                    pl[jj] = *(uint32_t*)&lb;
                }
#pragma unroll
                for (int ndp = 0; ndp < 8; ndp++) {
                    uint32_t boff = ((ndp * 16 + brow) * AVS + kc * 16 + bcol) * 2;
                    uint32_t rh[4], rl[4];
                    ldsm_x4(rh, uvh + boff);
                    ldsm_x4(rl, uvl + boff);
                    uint32_t b0h[2] = {rh[0], rh[1]}, b1h[2] = {rh[2], rh[3]};
                    uint32_t b0l[2] = {rl[0], rl[1]}, b1l[2] = {rl[2], rl[3]};
                    mma_bf16(oacc[2*ndp],   ph, b0h);
                    mma_bf16(oacc[2*ndp+1], ph, b1h);
                    mma_bf16(oacc[2*ndp],   pl, b0h);
                    mma_bf16(oacc[2*ndp+1], pl, b1h);
                    mma_bf16(oacc[2*ndp],   ph, b0l);
                    mma_bf16(oacc[2*ndp+1], ph, b1l);
                }
            }

            if (s == 0) MBAR_ARRIVE(mb_empty0); else MBAR_ARRIVE(mb_empty1);
        }

        MBAR_ARRIVE(mb_qfree);

        float i0 = 1.f / l0, i1 = 1.f / l1;
        size_t r0 = (size_t)(b * SEQ + gr0) * DIM + h * HD;
        size_t r1 = r0 + 8 * DIM;
#pragma unroll
        for (int nd = 0; nd < 16; nd++) {
            int col = nd * 8 + 2 * tig;
            split_store2(ohi, olo, (r0 + col) >> 1, oacc[nd][0] * i0, oacc[nd][1] * i0);
            split_store2(ohi, olo, (r1 + col) >> 1, oacc[nd][2] * i1, oacc[nd][3] * i1);
        }
    }
}

// ---------------- launcher ---------------------------------------------------
extern "C" void kernel_launch(void* const* d_in, const int* in_sizes, int n_in,
                              void* d_out, int out_size)
{
    const float* x    = (const float*)d_in[0];
    const float* w[4] = {(const float*)d_in[1], (const float*)d_in[2],
                         (const float*)d_in[3], (const float*)d_in[4]};
    const float* fcos = (const float*)d_in[5];
    const float* fsin = (const float*)d_in[6];
    float* out = (float*)d_out;

    __nv_bfloat16 *xhi, *xlo, *ohi, *olo, *whi, *wlo;
    __nv_bfloat16 *qhi, *qlo, *khi, *klo, *vthi, *vtlo;
    cudaGetSymbolAddress((void**)&xhi, g_xhi);
    cudaGetSymbolAddress((void**)&xlo, g_xlo);
    cudaGetSymbolAddress((void**)&ohi, g_ohi);
    cudaGetSymbolAddress((void**)&olo, g_olo);
    cudaGetSymbolAddress((void**)&whi, g_whi);
    cudaGetSymbolAddress((void**)&wlo, g_wlo);
    cudaGetSymbolAddress((void**)&qhi, g_qhi);
    cudaGetSymbolAddress((void**)&qlo, g_qlo);
    cudaGetSymbolAddress((void**)&khi, g_khi);
    cudaGetSymbolAddress((void**)&klo, g_klo);
    cudaGetSymbolAddress((void**)&vthi, g_vthi);
    cudaGetSymbolAddress((void**)&vtlo, g_vtlo);

    cudaFuncSetAttribute(gemm_qkv,
                         cudaFuncAttributeMaxDynamicSharedMemorySize, GEMM_SMEM_BYTES);
    cudaFuncSetAttribute(gemm_out,
                         cudaFuncAttributeMaxDynamicSharedMemorySize, GEMM_SMEM_BYTES);
    cudaFuncSetAttribute(attn_tc_kernel,
                         cudaFuncAttributeMaxDynamicSharedMemorySize, ATTN_SMEM_BYTES);

    int nx4 = ROWS * DIM / 4;
    int nw4 = DIM * DIM / 4;
    split_kernel<<<nx4 / 256, 256>>>(x, xhi, xlo, nx4);
    split4_kernel<<<dim3(nw4 / 256, 4), 256>>>(w[0], w[1], w[2], w[3], whi, wlo, nw4);

    dim3 gqkv(DIM / BN, ROWS / BM, 3);   // (16, 32, 3)
    gemm_qkv<<<gqkv, 384, GEMM_SMEM_BYTES>>>(
        xhi, xlo, whi, wlo, qhi, qlo, khi, klo, vthi, vtlo, fcos, fsin);

    attn_tc_kernel<<<NSM, 384, ATTN_SMEM_BYTES>>>(
        qhi, qlo, khi, klo, vthi, vtlo, ohi, olo);

    gemm_out<<<dim3(DIM / BN, ROWS / BM), 384, GEMM_SMEM_BYTES>>>(
        ohi, olo, whi + 3*(size_t)DIM*DIM, wlo + 3*(size_t)DIM*DIM, out);
}